// round 1
// baseline (speedup 1.0000x reference)
#include <cuda_runtime.h>
#include <cuda_bf16.h>
#include <math.h>

#define MDIM   4096
#define RANK   16
#define NROWS  1024
#define MMASK  (MDIM - 1)

// Scratch: softmax(H) rows. 16*4096 floats = 256 KB. Static device array (no alloc).
__device__ float g_S[RANK * MDIM];

// ---------------------------------------------------------------------------
// Kernel 1: row softmax of H (RANK x MDIM). One CTA per row, 256 threads.
// ---------------------------------------------------------------------------
__global__ void softmax_rows_kernel(const float* __restrict__ H) {
    const int r = blockIdx.x;
    const int t = threadIdx.x;
    const float* __restrict__ h = H + r * MDIM;
    float* __restrict__ s = g_S + r * MDIM;

    __shared__ float red[8];

    // --- row max ---
    float m = -3.402823e38f;
    #pragma unroll
    for (int i = 0; i < MDIM / 256; i++)
        m = fmaxf(m, h[t + i * 256]);
    #pragma unroll
    for (int o = 16; o > 0; o >>= 1)
        m = fmaxf(m, __shfl_xor_sync(0xffffffffu, m, o));
    if ((t & 31) == 0) red[t >> 5] = m;
    __syncthreads();
    float rowmax = red[0];
    #pragma unroll
    for (int i = 1; i < 8; i++) rowmax = fmaxf(rowmax, red[i]);
    __syncthreads();

    // --- exp + sum ---
    float acc = 0.0f;
    #pragma unroll
    for (int i = 0; i < MDIM / 256; i++) {
        float e = expf(h[t + i * 256] - rowmax);
        s[t + i * 256] = e;
        acc += e;
    }
    #pragma unroll
    for (int o = 16; o > 0; o >>= 1)
        acc += __shfl_xor_sync(0xffffffffu, acc, o);
    if ((t & 31) == 0) red[t >> 5] = acc;
    __syncthreads();
    float rowsum = 0.0f;
    #pragma unroll
    for (int i = 0; i < 8; i++) rowsum += red[i];
    float inv = 1.0f / rowsum;

    // --- normalize ---
    #pragma unroll
    for (int i = 0; i < MDIM / 256; i++)
        s[t + i * 256] *= inv;
}

// ---------------------------------------------------------------------------
// Kernel 2: out[n,k] = sum_r softplus(W[n,r]) * S[r, (k - tau[n,r]) & MMASK]
// One CTA per n. 256 threads; each thread handles 16 k's strided by 256
// (=> every warp LDG is a contiguous 128B L2-hit line within row r).
// ---------------------------------------------------------------------------
__global__ __launch_bounds__(256) void shiftnmf_main_kernel(
    const float* __restrict__ W,
    const int*   __restrict__ tau,
    float*       __restrict__ out)
{
    const int n = blockIdx.x;
    const int t = threadIdx.x;

    __shared__ float s_w[RANK];
    __shared__ int   s_t[RANK];
    if (t < RANK) {
        float w = W[n * RANK + t];
        // softplus, numerically fine for the uniform[0,1) inputs but stable anyway
        s_w[t] = (w > 20.0f) ? w : log1pf(expf(w));
        s_t[t] = tau[n * RANK + t];
    }
    __syncthreads();

    float acc[16];
    #pragma unroll
    for (int j = 0; j < 16; j++) acc[j] = 0.0f;

    #pragma unroll
    for (int r = 0; r < RANK; r++) {
        const float wr   = s_w[r];
        const int   base = t - s_t[r] + MDIM;      // >= 1, so & works directly
        const float* __restrict__ row = g_S + r * MDIM;
        #pragma unroll
        for (int j = 0; j < 16; j++) {
            int idx = (base + j * 256) & MMASK;
            acc[j] += wr * __ldg(&row[idx]);
        }
    }

    float* __restrict__ o = out + n * MDIM + t;
    #pragma unroll
    for (int j = 0; j < 16; j++)
        o[j * 256] = acc[j];
}

// ---------------------------------------------------------------------------
// Launch. Inputs per metadata order: W (N*RANK f32), H (RANK*M f32),
// tau (N*RANK i32). Output: N*M f32.
// ---------------------------------------------------------------------------
extern "C" void kernel_launch(void* const* d_in, const int* in_sizes, int n_in,
                              void* d_out, int out_size)
{
    const float* W   = (const float*)d_in[0];
    const float* H   = (const float*)d_in[1];
    const int*   tau = (const int*)d_in[2];
    float*       out = (float*)d_out;

    softmax_rows_kernel<<<RANK, 256>>>(H);
    shiftnmf_main_kernel<<<NROWS, 256>>>(W, tau, out);
}

// round 2
// speedup vs baseline: 1.0091x; 1.0091x over previous
#include <cuda_runtime.h>
#include <cuda_bf16.h>
#include <math.h>

#define MDIM   4096
#define RANK   16
#define NROWS  1024
#define MMASK  (MDIM - 1)

// Scratch: softmax(H) rows. 16*4096 floats = 256 KB. Static device array (no alloc).
__device__ float g_S[RANK * MDIM];

// ---------------------------------------------------------------------------
// Kernel 1: row softmax of H (RANK x MDIM). One CTA per row, 256 threads.
// ---------------------------------------------------------------------------
__global__ void softmax_rows_kernel(const float* __restrict__ H) {
    const int r = blockIdx.x;
    const int t = threadIdx.x;
    const float* __restrict__ h = H + r * MDIM;
    float* __restrict__ s = g_S + r * MDIM;

    __shared__ float red[8];

    // --- row max ---
    float m = -3.402823e38f;
    #pragma unroll
    for (int i = 0; i < MDIM / 256; i++)
        m = fmaxf(m, h[t + i * 256]);
    #pragma unroll
    for (int o = 16; o > 0; o >>= 1)
        m = fmaxf(m, __shfl_xor_sync(0xffffffffu, m, o));
    if ((t & 31) == 0) red[t >> 5] = m;
    __syncthreads();
    float rowmax = red[0];
    #pragma unroll
    for (int i = 1; i < 8; i++) rowmax = fmaxf(rowmax, red[i]);
    __syncthreads();

    // --- exp + sum ---
    float acc = 0.0f;
    #pragma unroll
    for (int i = 0; i < MDIM / 256; i++) {
        float e = expf(h[t + i * 256] - rowmax);
        s[t + i * 256] = e;
        acc += e;
    }
    #pragma unroll
    for (int o = 16; o > 0; o >>= 1)
        acc += __shfl_xor_sync(0xffffffffu, acc, o);
    if ((t & 31) == 0) red[t >> 5] = acc;
    __syncthreads();
    float rowsum = 0.0f;
    #pragma unroll
    for (int i = 0; i < 8; i++) rowsum += red[i];
    float inv = 1.0f / rowsum;

    // --- normalize ---
    #pragma unroll
    for (int i = 0; i < MDIM / 256; i++)
        s[t + i * 256] *= inv;
}

// ---------------------------------------------------------------------------
// Kernel 2: out[n,k] = sum_r softplus(W[n,r]) * S[r, (k - tau[n,r]) & MMASK]
// One CTA per n. 256 threads; each thread handles 16 k's strided by 256
// (=> every warp LDG is a contiguous 128B L2-hit line within row r).
// ---------------------------------------------------------------------------
__global__ __launch_bounds__(256) void shiftnmf_main_kernel(
    const float* __restrict__ W,
    const int*   __restrict__ tau,
    float*       __restrict__ out)
{
    const int n = blockIdx.x;
    const int t = threadIdx.x;

    __shared__ float s_w[RANK];
    __shared__ int   s_t[RANK];
    if (t < RANK) {
        float w = W[n * RANK + t];
        // softplus, numerically fine for the uniform[0,1) inputs but stable anyway
        s_w[t] = (w > 20.0f) ? w : log1pf(expf(w));
        s_t[t] = tau[n * RANK + t];
    }
    __syncthreads();

    float acc[16];
    #pragma unroll
    for (int j = 0; j < 16; j++) acc[j] = 0.0f;

    #pragma unroll
    for (int r = 0; r < RANK; r++) {
        const float wr   = s_w[r];
        const int   base = t - s_t[r] + MDIM;      // >= 1, so & works directly
        const float* __restrict__ row = g_S + r * MDIM;
        #pragma unroll
        for (int j = 0; j < 16; j++) {
            int idx = (base + j * 256) & MMASK;
            acc[j] += wr * __ldg(&row[idx]);
        }
    }

    float* __restrict__ o = out + n * MDIM + t;
    #pragma unroll
    for (int j = 0; j < 16; j++)
        o[j * 256] = acc[j];
}

// ---------------------------------------------------------------------------
// Launch. Inputs per metadata order: W (N*RANK f32), H (RANK*M f32),
// tau (N*RANK i32). Output: N*M f32.
// ---------------------------------------------------------------------------
extern "C" void kernel_launch(void* const* d_in, const int* in_sizes, int n_in,
                              void* d_out, int out_size)
{
    const float* W   = (const float*)d_in[0];
    const float* H   = (const float*)d_in[1];
    const int*   tau = (const int*)d_in[2];
    float*       out = (float*)d_out;

    softmax_rows_kernel<<<RANK, 256>>>(H);
    shiftnmf_main_kernel<<<NROWS, 256>>>(W, tau, out);
}